// round 14
// baseline (speedup 1.0000x reference)
#include <cuda_runtime.h>
#include <cuda_bf16.h>
#include <mma.h>
#include <cstdint>

using namespace nvcuda;

#define BQ    32
#define NN    512
#define MM    512
#define DFD   64
#define NDIAG 1023
#define NDPAD 1040          // padded (zero) so prefetch never clamps
#define TCH   8             // diagonals per chunk
#define TI    128           // dist tile rows (i)
#define TJ    128           // dist tile cols (j)
#define CPW   72            // active chunks per warp (trapezoid skip)
#define XPITCH 72           // bf16 smem pitch (mult of 8, bank-staggered)
#define DPITCH 132          // f32 smem pitch (132*4=528B mult of 16; 131 odd)

#define LOG2E 1.4426950408889634f
#define LN2   0.6931471805599453f
#define BIGS  1.4426950408889634e10f   // 1e10 * log2(e): self-maintaining in fp32
#define PROG_INF 100000

// Diagonal-major scaled distances: g_D[b][(i+j)][i] = log2e * ||x_i - y_j||^2.
// Zero-initialized; positions outside the valid band are never written.
__device__ float g_D[(size_t)BQ * NDPAD * NN];

// ---------------------------------------------------------------------------
__device__ __forceinline__ uint32_t smem_u32(const void* p) {
    return (uint32_t)__cvta_generic_to_shared(p);
}
__device__ __forceinline__ void st_release_cta(uint32_t addr, int v) {
    asm volatile("st.release.cta.shared.b32 [%0], %1;" :: "r"(addr), "r"(v) : "memory");
}
__device__ __forceinline__ int ld_acquire_cta(uint32_t addr) {
    int v;
    asm volatile("ld.acquire.cta.shared.b32 %0, [%1];" : "=r"(v) : "r"(addr) : "memory");
    return v;
}
__device__ __forceinline__ float ex2(float x) {
    float r; asm("ex2.approx.f32 %0, %1;" : "=f"(r) : "f"(x)); return r;
}
__device__ __forceinline__ float lg2(float x) {
    float r; asm("lg2.approx.f32 %0, %1;" : "=f"(r) : "f"(x)); return r;
}

// ---------------------------------------------------------------------------
// Kernel 1: pairwise squared distances via TENSOR-CORE Gram matrix.
// D' = log2e * (||x||^2 + ||y||^2 - 2 x.y); the cross-term X.Y^T is a
// 128x128x64 bf16 wmma GEMM per tile (norms stay fp32-exact). Output
// written diagonal-major. 8 warps: 4 (m) x 2 (n), warp tile 32x64.
// ---------------------------------------------------------------------------
__global__ void dist_kernel(const float* __restrict__ X,
                            const float* __restrict__ Y) {
    extern __shared__ char smraw[];
    __nv_bfloat16* Xs = (__nv_bfloat16*)smraw;           // [128][72]
    __nv_bfloat16* Ys = Xs + TI * XPITCH;                // [128][72]
    float* Dt = (float*)smraw;                           // [128][132] (reuse)
    __shared__ float xx[TI], yy[TJ];

    const int b  = blockIdx.z;
    const int i0 = blockIdx.y * TI;
    const int j0 = blockIdx.x * TJ;
    const int tid = threadIdx.x;

    const float* Xg = X + ((size_t)b * NN + i0) * DFD;
    const float* Yg = Y + ((size_t)b * MM + j0) * DFD;

    // Load + convert to bf16 (fp32 gmem reads, bf16 smem stores).
    #pragma unroll
    for (int idx = tid; idx < TI * DFD; idx += 256) {
        int r = idx >> 6, c = idx & 63;
        Xs[r * XPITCH + c] = __float2bfloat16(Xg[r * DFD + c]);
        Ys[r * XPITCH + c] = __float2bfloat16(Yg[r * DFD + c]);
    }

    // fp32-exact row norms (gmem re-read; L2-hot), pre-scaled by log2e.
    if (tid < TI + TJ) {
        const float* row = (tid < TI) ? (Xg + tid * DFD) : (Yg + (tid - TI) * DFD);
        float s = 0.f;
        #pragma unroll 8
        for (int k = 0; k < DFD; k++) s = fmaf(row[k], row[k], s);
        s *= LOG2E;
        if (tid < TI) xx[tid] = s; else yy[tid - TI] = s;
    }
    __syncthreads();

    // MMA mainloop: warp (wm, wn) computes rows [32wm, 32wm+32) x cols
    // [64wn, 64wn+64).
    const int wid = tid >> 5;
    const int wm  = wid & 3;
    const int wn  = wid >> 2;

    wmma::fragment<wmma::accumulator, 16, 16, 16, float> acc[2][4];
    #pragma unroll
    for (int u = 0; u < 2; u++)
        #pragma unroll
        for (int v = 0; v < 4; v++) wmma::fill_fragment(acc[u][v], 0.0f);

    #pragma unroll
    for (int kk = 0; kk < DFD; kk += 16) {
        wmma::fragment<wmma::matrix_a, 16, 16, 16, __nv_bfloat16,
                       wmma::row_major> af[2];
        wmma::fragment<wmma::matrix_b, 16, 16, 16, __nv_bfloat16,
                       wmma::col_major> bf[4];
        #pragma unroll
        for (int u = 0; u < 2; u++)
            wmma::load_matrix_sync(af[u],
                Xs + (32 * wm + 16 * u) * XPITCH + kk, XPITCH);
        #pragma unroll
        for (int v = 0; v < 4; v++)
            wmma::load_matrix_sync(bf[v],
                Ys + (64 * wn + 16 * v) * XPITCH + kk, XPITCH);
        #pragma unroll
        for (int u = 0; u < 2; u++)
            #pragma unroll
            for (int v = 0; v < 4; v++)
                wmma::mma_sync(acc[u][v], af[u], bf[v], acc[u][v]);
    }
    __syncthreads();   // all frags loaded; safe to overwrite Xs/Ys with Dt

    #pragma unroll
    for (int u = 0; u < 2; u++)
        #pragma unroll
        for (int v = 0; v < 4; v++)
            wmma::store_matrix_sync(
                Dt + (32 * wm + 16 * u) * DPITCH + 64 * wn + 16 * v,
                acc[u][v], DPITCH, wmma::mem_row_major);
    __syncthreads();

    // Combine with norms + coalesced diagonal-major writeback.
    // Diagonal read addr = ii*DPITCH + (dl-ii): stride 131 (odd) -> no conflicts.
    const int warp = tid >> 5, lane = tid & 31;
    const size_t base = (size_t)b * NDPAD * NN;
    for (int dl = warp; dl < TI + TJ - 1; dl += 8) {
        int lo = dl - (TJ - 1); if (lo < 0) lo = 0;
        int hi = dl;            if (hi > TI - 1) hi = TI - 1;
        for (int ii = lo + lane; ii <= hi; ii += 32) {
            int jj = dl - ii;
            int gi = i0 + ii;
            int gj = j0 + jj;
            g_D[base + (size_t)(gi + gj) * NN + gi] =
                fmaf(-2.0f * LOG2E, Dt[ii * DPITCH + jj], xx[ii] + yy[jj]);
        }
    }
}

// ---------------------------------------------------------------------------
// Soft-min cell, log2 domain, (p,q) presorted, late input last.
// ---------------------------------------------------------------------------
__device__ __forceinline__ float cell(float p, float q, float late, float Dv) {
    const float m   = fminf(p, late);
    const float mid = fminf(q, fmaxf(p, late));
    const float top = fmaxf(q, late);
    const float s   = 1.0f + ex2(m - mid) + ex2(m - top);
    return Dv + m - lg2(s);
}

// ---------------------------------------------------------------------------
// Kernel 2: warp-pipelined wavefront with trapezoid skip (R13, unchanged).
// ---------------------------------------------------------------------------
__global__ void __launch_bounds__(256, 1)
dp_kernel(const int* __restrict__ X_len, const int* __restrict__ Y_len,
          float* __restrict__ out) {
    __shared__ float edge[8][1032];    // edge[w][d] = R'[d][64(w+1)]
    __shared__ float nb[8][32];        // per-warp lane ring of cur_hi
    __shared__ int   prog[8];

    const int b    = blockIdx.x;
    const int tid  = threadIdx.x;
    const int w    = tid >> 5;
    const int lane = tid & 31;
    const int i_lo = 2 * tid + 1;
    const int i_hi = i_lo + 1;

    const int xl  = X_len[b];
    const int tot = xl + Y_len[b];
    const bool wantlo = (xl == i_lo);
    const bool wanthi = (xl == i_hi);
    const bool isl0   = (lane == 0);
    const bool isl31  = (lane == 31);
    const int  nlane  = (lane == 0) ? 31 : lane - 1;

    for (int idx = tid; idx < 8 * 1032; idx += 256)
        ((float*)edge)[idx] = BIGS;
    if (tid < 8) prog[tid] = 1;
    nb[w][lane] = BIGS;
    __syncthreads();                    // the only CTA barrier

    const uint32_t prog_self = smem_u32(&prog[w]);
    const uint32_t prog_prev = smem_u32(&prog[(w == 0) ? 0 : w - 1]);

    const float2* Dp = (const float2*)(g_D + (size_t)b * NDPAD * NN) + tid;

    const int c0 = 8 * w;
    const int c1 = 8 * w + CPW - 1;

    float2 Dc[TCH];
    #pragma unroll
    for (int k = 0; k < TCH; ++k)
        Dc[k] = Dp[(size_t)(TCH * c0 + k) * 256];

    float r1_lo = BIGS, r1_hi = BIGS;
    float p_lo = (tid == 0) ? 0.0f : BIGS, q_lo = BIGS;
    float p_hi = BIGS, q_hi = BIGS;
    float res = 0.0f;

    for (int c = c0; c <= c1; ++c) {
        const int d0 = 2 + TCH * c;

        float2 Dn[TCH];
        #pragma unroll
        for (int k = 0; k < TCH; ++k)
            Dn[k] = Dp[(size_t)(TCH * (c + 1) + k) * 256];

        float e[TCH];
        if (w > 0) {
            const int needed = d0 + TCH - 2;
            while (ld_acquire_cta(prog_prev) < needed) __nanosleep(64);
            #pragma unroll
            for (int k = 0; k < TCH; ++k) e[k] = edge[w - 1][d0 - 1 + k];
        } else {
            #pragma unroll
            for (int k = 0; k < TCH; ++k) e[k] = BIGS;
        }

        if ((unsigned)(tot - d0) < TCH) {
            #pragma unroll
            for (int k = 0; k < TCH; ++k) {
                const int d = d0 + k;
                const float nbv = nb[w][nlane];

                const float cur_hi = cell(p_hi, q_hi, r1_hi, Dc[k].y);
                nb[w][lane] = cur_hi;
                if (isl31) edge[w][d] = cur_hi;

                const float tmp = isl0 ? e[k] : nbv;
                const float cur_lo = cell(p_lo, q_lo, tmp, Dc[k].x);

                if (d == tot)
                    res = wantlo ? cur_lo : (wanthi ? cur_hi : res);

                p_hi = fminf(r1_lo, cur_lo);
                q_hi = fmaxf(r1_lo, cur_lo);
                p_lo = fminf(tmp, cur_lo);
                q_lo = fmaxf(tmp, cur_lo);
                r1_lo = cur_lo;
                r1_hi = cur_hi;
            }
        } else {
            #pragma unroll
            for (int k = 0; k < TCH; ++k) {
                const int d = d0 + k;
                const float nbv = nb[w][nlane];

                const float cur_hi = cell(p_hi, q_hi, r1_hi, Dc[k].y);
                nb[w][lane] = cur_hi;
                if (isl31) edge[w][d] = cur_hi;

                const float tmp = isl0 ? e[k] : nbv;
                const float cur_lo = cell(p_lo, q_lo, tmp, Dc[k].x);

                p_hi = fminf(r1_lo, cur_lo);
                q_hi = fmaxf(r1_lo, cur_lo);
                p_lo = fminf(tmp, cur_lo);
                q_lo = fmaxf(tmp, cur_lo);
                r1_lo = cur_lo;
                r1_hi = cur_hi;
            }
        }

        if (w < 7 && isl31)
            st_release_cta(prog_self, d0 + TCH - 1);   // orders edge STS

        #pragma unroll
        for (int k = 0; k < TCH; ++k) Dc[k] = Dn[k];
    }

    if (w < 7 && isl31)
        st_release_cta(prog_self, PROG_INF);

    if (wantlo | wanthi) out[b] = res * LN2;
}

// ---------------------------------------------------------------------------
extern "C" void kernel_launch(void* const* d_in, const int* in_sizes, int n_in,
                              void* d_out, int out_size) {
    const float* X     = (const float*)d_in[0];
    const float* Y     = (const float*)d_in[1];
    const int*   X_len = (const int*)d_in[2];
    const int*   Y_len = (const int*)d_in[3];
    float*       out   = (float*)d_out;

    const int dist_smem = TI * DPITCH * 4;   // 67584 B (>= bf16 tiles 36864 B)
    static bool attr_set = false;
    if (!attr_set) {
        cudaFuncSetAttribute(dist_kernel,
                             cudaFuncAttributeMaxDynamicSharedMemorySize,
                             dist_smem);
        attr_set = true;
    }

    dist_kernel<<<dim3(MM / TJ, NN / TI, BQ), 256, dist_smem>>>(X, Y);
    dp_kernel<<<BQ, 256>>>(X_len, Y_len, out);
}